// round 2
// baseline (speedup 1.0000x reference)
#include <cuda_runtime.h>

// EdgeDecoder: out[e] = relu(concat(user[i], movie[j]) @ w1^T + b1) @ w2^T + b2
// Restructured:
//   U[i] = user_emb[i]  @ w1[:, :128]^T + b1   (precomputed, all users)
//   M[j] = movie_emb[j] @ w1[:, 128:]^T        (precomputed, all movies)
//   out[e] = relu(U[i]+M[j]) . w2 + b2

#define HIDDEN      128
#define MAX_USERS   100000
#define MAX_MOVIES  50000
#define WT_STRIDE   132            // padded row stride for transposed w1 in smem
#define PRE_THREADS 256
#define SMEM_FLOATS (HIDDEN * WT_STRIDE + 8 * 4 * HIDDEN)

__device__ __align__(16) float g_U[(size_t)MAX_USERS  * HIDDEN];
__device__ __align__(16) float g_M[(size_t)MAX_MOVIES * HIDDEN];
__device__ int g_idx_is_i64;   // 1 if edge index buffer is int64, 0 if int32

// ---------------------------------------------------------------------------
// Probe: decide whether the edge-index buffer is int64 or int32.
// Viewed as int32, little-endian int64 data (values < 2^31) has ALL odd
// words == 0. Genuine int32 index data has random values at odd positions;
// P(128 consecutive odd words all zero) is ~0. Deterministic per launch.
// ---------------------------------------------------------------------------
__global__ void probe_kernel(const int* __restrict__ ei32)
{
    if (threadIdx.x == 0 && blockIdx.x == 0) {
        int all_zero = 1;
        #pragma unroll 8
        for (int k = 1; k < 256; k += 2)
            if (ei32[k] != 0) { all_zero = 0; break; }
        g_idx_is_i64 = all_zero;
    }
}

// ---------------------------------------------------------------------------
// Precompute kernel: blocks [0, g_user) do the user table (koff=0, +b1),
// blocks [g_user, grid) do the movie table (koff=128, no bias).
// Each warp handles 4 rows at a time; lane l computes outputs j = 4l..4l+3.
// ---------------------------------------------------------------------------
__global__ __launch_bounds__(PRE_THREADS, 2)
void precompute_kernel(const float* __restrict__ user_emb,
                       const float* __restrict__ movie_emb,
                       const float* __restrict__ w1,
                       const float* __restrict__ b1,
                       int n_users, int n_movies, int g_user)
{
    extern __shared__ float smem[];
    float* wT = smem;                         // [128][WT_STRIDE]
    float* xs = smem + HIDDEN * WT_STRIDE;    // [8 warps][4 rows][128]

    const float* emb;
    float*       outT;
    int nrows, koff, addBias, bx, gsz;
    if ((int)blockIdx.x < g_user) {
        emb = user_emb;  outT = g_U; nrows = n_users;  koff = 0;      addBias = 1;
        bx = blockIdx.x;           gsz = g_user;
    } else {
        emb = movie_emb; outT = g_M; nrows = n_movies; koff = HIDDEN; addBias = 0;
        bx = blockIdx.x - g_user;  gsz = gridDim.x - g_user;
    }

    // Stage the relevant 128x128 half of w1, transposed: wT[k][j] = w1[j][koff+k]
    for (int idx = threadIdx.x; idx < HIDDEN * HIDDEN; idx += PRE_THREADS) {
        int j = idx >> 7;               // output index
        int k = idx & (HIDDEN - 1);     // reduction index (coalesced gmem read)
        wT[k * WT_STRIDE + j] = w1[j * (2 * HIDDEN) + koff + k];
    }
    __syncthreads();

    int warp = threadIdx.x >> 5;
    int lane = threadIdx.x & 31;
    float* xw = xs + warp * (4 * HIDDEN);

    float4 bias = make_float4(0.f, 0.f, 0.f, 0.f);
    if (addBias) bias = ((const float4*)b1)[lane];

    int ngroups = (nrows + 3) >> 2;
    for (int g = bx * 8 + warp; g < ngroups; g += gsz * 8) {
        int row0 = g * 4;

        // stage 4 input rows (coalesced float4 loads)
        #pragma unroll
        for (int r = 0; r < 4; r++) {
            int row = row0 + r;
            float4 v = make_float4(0.f, 0.f, 0.f, 0.f);
            if (row < nrows)
                v = ((const float4*)(emb + (size_t)row * HIDDEN))[lane];
            ((float4*)(xw + r * HIDDEN))[lane] = v;
        }
        __syncwarp();

        float4 a0 = make_float4(0.f,0.f,0.f,0.f);
        float4 a1 = a0, a2 = a0, a3 = a0;

        #pragma unroll 4
        for (int k = 0; k < HIDDEN; k++) {
            float4 w = *(const float4*)(wT + k * WT_STRIDE + 4 * lane);
            float x0 = xw[0 * HIDDEN + k];
            float x1 = xw[1 * HIDDEN + k];
            float x2 = xw[2 * HIDDEN + k];
            float x3 = xw[3 * HIDDEN + k];
            a0.x = fmaf(x0, w.x, a0.x); a0.y = fmaf(x0, w.y, a0.y);
            a0.z = fmaf(x0, w.z, a0.z); a0.w = fmaf(x0, w.w, a0.w);
            a1.x = fmaf(x1, w.x, a1.x); a1.y = fmaf(x1, w.y, a1.y);
            a1.z = fmaf(x1, w.z, a1.z); a1.w = fmaf(x1, w.w, a1.w);
            a2.x = fmaf(x2, w.x, a2.x); a2.y = fmaf(x2, w.y, a2.y);
            a2.z = fmaf(x2, w.z, a2.z); a2.w = fmaf(x2, w.w, a2.w);
            a3.x = fmaf(x3, w.x, a3.x); a3.y = fmaf(x3, w.y, a3.y);
            a3.z = fmaf(x3, w.z, a3.z); a3.w = fmaf(x3, w.w, a3.w);
        }

        float4 accs[4] = {a0, a1, a2, a3};
        #pragma unroll
        for (int r = 0; r < 4; r++) {
            int row = row0 + r;
            if (row < nrows) {
                float4 o;
                o.x = accs[r].x + bias.x;
                o.y = accs[r].y + bias.y;
                o.z = accs[r].z + bias.z;
                o.w = accs[r].w + bias.w;
                ((float4*)(outT + (size_t)row * HIDDEN))[lane] = o;
            }
        }
        __syncwarp();   // protect xs before next iteration's restage
    }
}

// ---------------------------------------------------------------------------
// Edge kernel: one warp per edge. Lane l holds elements 4l..4l+3 of the
// hidden vector. Coalesced 512B row reads of U[i] and M[j] (L2-resident),
// relu+dot with w2, butterfly reduce, lane 0 writes the scalar.
// Index dtype resolved at runtime via g_idx_is_i64; indices clamped so a
// wrong interpretation yields wrong values (rel_err signal), never a fault.
// ---------------------------------------------------------------------------
__global__ __launch_bounds__(256)
void edge_kernel(const int* __restrict__ ei32,
                 const float* __restrict__ w2,
                 const float* __restrict__ b2,
                 float* __restrict__ out, int E,
                 int n_users, int n_movies)
{
    int lane = threadIdx.x & 31;
    int warp = (int)((blockIdx.x * blockDim.x + threadIdx.x) >> 5);
    int nw   = (int)((gridDim.x * blockDim.x) >> 5);

    const int mode64 = g_idx_is_i64;
    float4 wv = ((const float4*)w2)[lane];
    float  bb = b2[0];
    const float4* U4 = (const float4*)g_U;
    const float4* M4 = (const float4*)g_M;

    for (int e = warp; e < E; e += nw) {
        int iu, im;
        if (mode64) {
            iu = ei32[2 * e];              // low word of int64 edge[0][e]
            im = ei32[2 * (E + e)];        // low word of int64 edge[1][e]
        } else {
            iu = ei32[e];
            im = ei32[E + e];
        }
        // clamp: crash-proof regardless of dtype interpretation
        iu = min(max(iu, 0), n_users  - 1);
        im = min(max(im, 0), n_movies - 1);

        float4 u = U4[(size_t)iu * 32 + lane];
        float4 m = M4[(size_t)im * 32 + lane];

        float s;
        s = fmaxf(u.x + m.x, 0.f) * wv.x;
        s = fmaf(fmaxf(u.y + m.y, 0.f), wv.y, s);
        s = fmaf(fmaxf(u.z + m.z, 0.f), wv.z, s);
        s = fmaf(fmaxf(u.w + m.w, 0.f), wv.w, s);

        s += __shfl_xor_sync(0xffffffffu, s, 16);
        s += __shfl_xor_sync(0xffffffffu, s, 8);
        s += __shfl_xor_sync(0xffffffffu, s, 4);
        s += __shfl_xor_sync(0xffffffffu, s, 2);
        s += __shfl_xor_sync(0xffffffffu, s, 1);

        if (lane == 0) out[e] = s + bb;
    }
}

// ---------------------------------------------------------------------------
extern "C" void kernel_launch(void* const* d_in, const int* in_sizes, int n_in,
                              void* d_out, int out_size)
{
    const float* user_emb  = (const float*)d_in[0];
    const float* movie_emb = (const float*)d_in[1];
    const int*   ei32      = (const int*)d_in[2];
    const float* w1        = (const float*)d_in[3];
    const float* b1        = (const float*)d_in[4];
    const float* w2        = (const float*)d_in[5];
    const float* b2        = (const float*)d_in[6];
    float*       out       = (float*)d_out;

    int n_users  = in_sizes[0] / HIDDEN;
    int n_movies = in_sizes[1] / HIDDEN;
    if (n_users  > MAX_USERS)  n_users  = MAX_USERS;
    if (n_movies > MAX_MOVIES) n_movies = MAX_MOVIES;
    int E = out_size;                       // out is [E, 1]

    size_t smem_bytes = (size_t)SMEM_FLOATS * sizeof(float);   // 83968 B
    cudaFuncSetAttribute(precompute_kernel,
                         cudaFuncAttributeMaxDynamicSharedMemorySize,
                         (int)smem_bytes);

    probe_kernel<<<1, 32>>>(ei32);

    // ~2 blocks/SM resident at 84KB smem; split grid ~2:1 user:movie.
    const int g_user = 592, g_movie = 296;
    precompute_kernel<<<g_user + g_movie, PRE_THREADS, smem_bytes>>>(
        user_emb, movie_emb, w1, b1, n_users, n_movies, g_user);

    edge_kernel<<<2048, 256>>>(ei32, w2, b2, out, E, n_users, n_movies);
}

// round 3
// speedup vs baseline: 1.1915x; 1.1915x over previous
#include <cuda_runtime.h>

// EdgeDecoder: out[e] = relu(concat(user[i], movie[j]) @ w1^T + b1) @ w2^T + b2
// Restructured:
//   U[i] = user_emb[i]  @ w1[:, :128]^T + b1   (precomputed, referenced rows only)
//   M[j] = movie_emb[j] @ w1[:, 128:]^T        (precomputed, referenced rows only)
//   out[e] = relu(U[i]+M[j]) . w2 + b2
// Precompute mainloop uses fp32x2 packed FMA (exact fp32, 2x FFMA throughput).

#define HIDDEN      128
#define MAX_USERS   100000
#define MAX_MOVIES  50000
#define WT_STRIDE   132            // padded row stride for transposed w1 in smem
#define PRE_THREADS 256
#define SMEM_FLOATS (HIDDEN * WT_STRIDE + 8 * 4 * HIDDEN)

__device__ __align__(16) float g_U[(size_t)MAX_USERS  * HIDDEN];
__device__ __align__(16) float g_M[(size_t)MAX_MOVIES * HIDDEN];
__device__ int g_idx_is_i64;   // 1 if edge index buffer is int64, 0 if int32
__device__ int g_max_user;     // max referenced user index (exact)
__device__ int g_max_movie;    // max referenced movie index (exact)

__device__ __forceinline__ unsigned long long pack2(float x) {
    unsigned long long r;
    asm("mov.b64 %0, {%1, %1};" : "=l"(r) : "f"(x));
    return r;
}
__device__ __forceinline__ void ffma2(unsigned long long& acc,
                                      unsigned long long w,
                                      unsigned long long x) {
    asm("fma.rn.f32x2 %0, %1, %2, %0;" : "+l"(acc) : "l"(w), "l"(x));
}
__device__ __forceinline__ float2 unpack2(unsigned long long v) {
    float lo, hi;
    asm("mov.b64 {%0, %1}, %2;" : "=f"(lo), "=f"(hi) : "l"(v));
    return make_float2(lo, hi);
}

// ---------------------------------------------------------------------------
// Init+probe: decide int64 vs int32 view of the edge-index buffer, and zero
// the max accumulators. Little-endian int64 (values < 2^31) has all odd
// int32 words == 0; genuine int32 index data essentially never does.
// ---------------------------------------------------------------------------
__global__ void init_probe_kernel(const int* __restrict__ ei32)
{
    if (threadIdx.x == 0) {
        int all_zero = 1;
        #pragma unroll 8
        for (int k = 1; k < 256; k += 2)
            if (ei32[k] != 0) { all_zero = 0; break; }
        g_idx_is_i64 = all_zero;
        g_max_user   = 0;
        g_max_movie  = 0;
    }
}

// ---------------------------------------------------------------------------
// Exact max-index reduction over both index rows. Block-level smem reduce,
// two atomicMax per block.
// ---------------------------------------------------------------------------
__global__ __launch_bounds__(256)
void reduce_max_kernel(const int* __restrict__ ei32, int E)
{
    __shared__ int s_u[8], s_m[8];
    const int mode64 = g_idx_is_i64;
    int tid  = blockIdx.x * blockDim.x + threadIdx.x;
    int nthr = gridDim.x * blockDim.x;

    int mu = 0, mm = 0;
    for (int e = tid; e < E; e += nthr) {
        int iu, im;
        if (mode64) { iu = ei32[2 * e]; im = ei32[2 * (E + e)]; }
        else        { iu = ei32[e];     im = ei32[E + e]; }
        mu = max(mu, iu);
        mm = max(mm, im);
    }
    #pragma unroll
    for (int o = 16; o > 0; o >>= 1) {
        mu = max(mu, __shfl_xor_sync(0xffffffffu, mu, o));
        mm = max(mm, __shfl_xor_sync(0xffffffffu, mm, o));
    }
    int warp = threadIdx.x >> 5, lane = threadIdx.x & 31;
    if (lane == 0) { s_u[warp] = mu; s_m[warp] = mm; }
    __syncthreads();
    if (threadIdx.x == 0) {
        int bu = s_u[0], bm = s_m[0];
        #pragma unroll
        for (int w = 1; w < 8; w++) { bu = max(bu, s_u[w]); bm = max(bm, s_m[w]); }
        atomicMax(&g_max_user, bu);
        atomicMax(&g_max_movie, bm);
    }
}

// ---------------------------------------------------------------------------
// Precompute kernel: blocks [0, g_user) do the user table (koff=0, +b1),
// blocks [g_user, grid) do the movie table (koff=128, no bias).
// Each warp handles 4 rows; lane l computes outputs j = 4l..4l+3 using
// packed f32x2 FMA (two outputs per instruction).
// ---------------------------------------------------------------------------
__global__ __launch_bounds__(PRE_THREADS, 2)
void precompute_kernel(const float* __restrict__ user_emb,
                       const float* __restrict__ movie_emb,
                       const float* __restrict__ w1,
                       const float* __restrict__ b1,
                       int n_users, int n_movies, int g_user)
{
    extern __shared__ float smem[];
    float* wT = smem;                         // [128][WT_STRIDE]
    float* xs = smem + HIDDEN * WT_STRIDE;    // [8 warps][4 rows][128]

    const float* emb;
    float*       outT;
    int nrows, koff, addBias, bx, gsz;
    if ((int)blockIdx.x < g_user) {
        emb = user_emb;  outT = g_U;
        nrows = min(n_users, g_max_user + 1);
        koff = 0; addBias = 1;
        bx = blockIdx.x; gsz = g_user;
    } else {
        emb = movie_emb; outT = g_M;
        nrows = min(n_movies, g_max_movie + 1);
        koff = HIDDEN; addBias = 0;
        bx = blockIdx.x - g_user; gsz = gridDim.x - g_user;
    }

    // Stage the relevant 128x128 half of w1, transposed: wT[k][j] = w1[j][koff+k]
    for (int idx = threadIdx.x; idx < HIDDEN * HIDDEN; idx += PRE_THREADS) {
        int j = idx >> 7;               // output index
        int k = idx & (HIDDEN - 1);     // reduction index (coalesced gmem read)
        wT[k * WT_STRIDE + j] = w1[j * (2 * HIDDEN) + koff + k];
    }
    __syncthreads();

    int warp = threadIdx.x >> 5;
    int lane = threadIdx.x & 31;
    float* xw = xs + warp * (4 * HIDDEN);

    float4 bias = make_float4(0.f, 0.f, 0.f, 0.f);
    if (addBias) bias = ((const float4*)b1)[lane];

    int ngroups = (nrows + 3) >> 2;
    for (int g = bx * 8 + warp; g < ngroups; g += gsz * 8) {
        int row0 = g * 4;

        // stage 4 input rows (coalesced float4 loads)
        #pragma unroll
        for (int r = 0; r < 4; r++) {
            int row = row0 + r;
            float4 v = make_float4(0.f, 0.f, 0.f, 0.f);
            if (row < nrows)
                v = ((const float4*)(emb + (size_t)row * HIDDEN))[lane];
            ((float4*)(xw + r * HIDDEN))[lane] = v;
        }
        __syncwarp();

        // accumulators: 4 rows x 2 packed pairs (outputs 4l..4l+1, 4l+2..4l+3)
        unsigned long long a[4][2];
        #pragma unroll
        for (int r = 0; r < 4; r++) { a[r][0] = 0ull; a[r][1] = 0ull; }

        const float* wrow = wT + 4 * lane;
        #pragma unroll 4
        for (int k = 0; k < HIDDEN; k++) {
            ulonglong2 w = *(const ulonglong2*)(wrow + k * WT_STRIDE);
            unsigned long long x0 = pack2(xw[0 * HIDDEN + k]);
            unsigned long long x1 = pack2(xw[1 * HIDDEN + k]);
            unsigned long long x2 = pack2(xw[2 * HIDDEN + k]);
            unsigned long long x3 = pack2(xw[3 * HIDDEN + k]);
            ffma2(a[0][0], w.x, x0); ffma2(a[0][1], w.y, x0);
            ffma2(a[1][0], w.x, x1); ffma2(a[1][1], w.y, x1);
            ffma2(a[2][0], w.x, x2); ffma2(a[2][1], w.y, x2);
            ffma2(a[3][0], w.x, x3); ffma2(a[3][1], w.y, x3);
        }

        #pragma unroll
        for (int r = 0; r < 4; r++) {
            int row = row0 + r;
            if (row < nrows) {
                float2 lo = unpack2(a[r][0]);
                float2 hi = unpack2(a[r][1]);
                float4 o;
                o.x = lo.x + bias.x;
                o.y = lo.y + bias.y;
                o.z = hi.x + bias.z;
                o.w = hi.y + bias.w;
                ((float4*)(outT + (size_t)row * HIDDEN))[lane] = o;
            }
        }
        __syncwarp();   // protect xs before next iteration's restage
    }
}

// ---------------------------------------------------------------------------
// Edge kernel: one warp per edge. Lane l holds elements 4l..4l+3 of the
// hidden vector. Coalesced 512B row reads of U[i] and M[j] (L2-resident),
// relu+dot with w2, butterfly reduce, lane 0 writes the scalar.
// ---------------------------------------------------------------------------
__global__ __launch_bounds__(256)
void edge_kernel(const int* __restrict__ ei32,
                 const float* __restrict__ w2,
                 const float* __restrict__ b2,
                 float* __restrict__ out, int E,
                 int n_users, int n_movies)
{
    int lane = threadIdx.x & 31;
    int warp = (int)((blockIdx.x * blockDim.x + threadIdx.x) >> 5);
    int nw   = (int)((gridDim.x * blockDim.x) >> 5);

    const int mode64 = g_idx_is_i64;
    float4 wv = ((const float4*)w2)[lane];
    float  bb = b2[0];
    const float4* U4 = (const float4*)g_U;
    const float4* M4 = (const float4*)g_M;

    for (int e = warp; e < E; e += nw) {
        int iu, im;
        if (mode64) {
            iu = ei32[2 * e];              // low word of int64 edge[0][e]
            im = ei32[2 * (E + e)];        // low word of int64 edge[1][e]
        } else {
            iu = ei32[e];
            im = ei32[E + e];
        }
        // clamp: crash-proof regardless of dtype interpretation
        iu = min(max(iu, 0), n_users  - 1);
        im = min(max(im, 0), n_movies - 1);

        float4 u = U4[(size_t)iu * 32 + lane];
        float4 m = M4[(size_t)im * 32 + lane];

        float s;
        s = fmaxf(u.x + m.x, 0.f) * wv.x;
        s = fmaf(fmaxf(u.y + m.y, 0.f), wv.y, s);
        s = fmaf(fmaxf(u.z + m.z, 0.f), wv.z, s);
        s = fmaf(fmaxf(u.w + m.w, 0.f), wv.w, s);

        s += __shfl_xor_sync(0xffffffffu, s, 16);
        s += __shfl_xor_sync(0xffffffffu, s, 8);
        s += __shfl_xor_sync(0xffffffffu, s, 4);
        s += __shfl_xor_sync(0xffffffffu, s, 2);
        s += __shfl_xor_sync(0xffffffffu, s, 1);

        if (lane == 0) out[e] = s + bb;
    }
}

// ---------------------------------------------------------------------------
extern "C" void kernel_launch(void* const* d_in, const int* in_sizes, int n_in,
                              void* d_out, int out_size)
{
    const float* user_emb  = (const float*)d_in[0];
    const float* movie_emb = (const float*)d_in[1];
    const int*   ei32      = (const int*)d_in[2];
    const float* w1        = (const float*)d_in[3];
    const float* b1        = (const float*)d_in[4];
    const float* w2        = (const float*)d_in[5];
    const float* b2        = (const float*)d_in[6];
    float*       out       = (float*)d_out;

    int n_users  = in_sizes[0] / HIDDEN;
    int n_movies = in_sizes[1] / HIDDEN;
    if (n_users  > MAX_USERS)  n_users  = MAX_USERS;
    if (n_movies > MAX_MOVIES) n_movies = MAX_MOVIES;
    int E = out_size;                       // out is [E, 1]

    size_t smem_bytes = (size_t)SMEM_FLOATS * sizeof(float);   // 83968 B
    cudaFuncSetAttribute(precompute_kernel,
                         cudaFuncAttributeMaxDynamicSharedMemorySize,
                         (int)smem_bytes);

    init_probe_kernel<<<1, 32>>>(ei32);
    reduce_max_kernel<<<256, 256>>>(ei32, E);

    // ~2 blocks/SM resident at 84KB smem; both tables ~equal referenced rows.
    const int g_user = 444, g_movie = 444;
    precompute_kernel<<<g_user + g_movie, PRE_THREADS, smem_bytes>>>(
        user_emb, movie_emb, w1, b1, n_users, n_movies, g_user);

    edge_kernel<<<2048, 256>>>(ei32, w2, b2, out, E, n_users, n_movies);
}